// round 1
// baseline (speedup 1.0000x reference)
#include <cuda_runtime.h>

#define Nn 20000
#define Fc 64
#define Zs 10
#define Ee 320000

// ---- scratch (device globals; no allocation) ----
__device__ float4 d_up[Nn * Fc];      // packed (s, v0, v1, v2), inv folded
__device__ float4 d_skip[Nn * Fc];    // packed skip (s, v0, v1, v2), inv folded
__device__ float4 d_acc[Nn * Fc];     // message accumulator (s, v0, v1, v2)
__device__ float  d_wsc[Zs * 9 * Fc]; // Wsc projected: [(z*9+b)*64+u]
__device__ int    d_cum[Zs + 1];

constexpr float INV  = 0.125f;  // 1/sqrt(64)
constexpr float EPSC = 0.25f;

__device__ __forceinline__ float silu(float x) {
    return __fdividef(x, 1.0f + __expf(-x));
}

// ---- k0: species prefix + Wsc @ Proj ----
__global__ void k0(const int* __restrict__ counts,
                   const float* __restrict__ Wsc,
                   const float* __restrict__ Proj) {
    int tid = threadIdx.x;
    if (tid == 0) {
        int c = 0; d_cum[0] = 0;
        for (int z = 0; z < Zs; z++) { c += counts[z]; d_cum[z + 1] = c; }
    }
    for (int it = tid; it < Zs * 9 * Fc; it += blockDim.x) {
        int z = it / (9 * Fc);
        int rem = it % (9 * Fc);
        int b = rem / Fc, u = rem % Fc;
        float s = 0.f;
        #pragma unroll
        for (int p = 0; p < 9; p++)
            s += Wsc[(z * 9 + p) * Fc + u] * Proj[p * 9 + b];
        d_wsc[it] = s;  // layout (z*9+b)*64+u
    }
}

// ---- kA: linear_up + species skip (8 nodes / 256-thread block) ----
__global__ void __launch_bounds__(256) kA(
    const float* __restrict__ node_s, const float* __restrict__ node_v,
    const float* __restrict__ Wup0, const float* __restrict__ Wup1,
    const float* __restrict__ Ws0, const float* __restrict__ Ws1) {
    __shared__ float s_sm[512];
    __shared__ float v_sm[1536];
    __shared__ int zc[8];
    int tid = threadIdx.x;
    int n0 = blockIdx.x * 8;

    for (int i = tid; i < 512; i += 256)  s_sm[i] = node_s[n0 * 64 + i];
    for (int i = tid; i < 1536; i += 256) v_sm[i] = node_v[n0 * 192 + i];
    if (tid < 8) {
        int n = n0 + tid, z = 0;
        #pragma unroll
        for (int q = 1; q < Zs; q++) z += (n >= d_cum[q]);
        zc[tid] = z;
    }
    {   // zero accumulator rows for these 8 nodes
        float* accf = (float*)d_acc;
        for (int i = tid; i < 2048; i += 256) accf[n0 * 256 + i] = 0.f;
    }
    __syncthreads();

    int g = tid & 63, grp = tid >> 6;
    int la = grp * 2, lb = la + 1;
    const float* w0p = Wup0 + g;
    const float* w1p = Wup1 + g;
    const float* a0p = Ws0 + zc[la] * 4096 + g;
    const float* a1p = Ws1 + zc[la] * 4096 + g;
    const float* b0p = Ws0 + zc[lb] * 4096 + g;
    const float* b1p = Ws1 + zc[lb] * 4096 + g;

    float uA = 0, uB = 0, skA = 0, skB = 0;
    float3 vuA = {0,0,0}, vuB = {0,0,0}, vkA = {0,0,0}, vkB = {0,0,0};
    #pragma unroll 4
    for (int f = 0; f < 64; f++) {
        float wu0 = w0p[f * 64], wu1 = w1p[f * 64];
        float wa0 = a0p[f * 64], wa1 = a1p[f * 64];
        float wb0 = b0p[f * 64], wb1 = b1p[f * 64];
        float sA = s_sm[la * 64 + f], sB = s_sm[lb * 64 + f];
        float vA0 = v_sm[(la * 64 + f) * 3 + 0];
        float vA1 = v_sm[(la * 64 + f) * 3 + 1];
        float vA2 = v_sm[(la * 64 + f) * 3 + 2];
        float vB0 = v_sm[(lb * 64 + f) * 3 + 0];
        float vB1 = v_sm[(lb * 64 + f) * 3 + 1];
        float vB2 = v_sm[(lb * 64 + f) * 3 + 2];
        uA += wu0 * sA;  skA += wa0 * sA;
        uB += wu0 * sB;  skB += wb0 * sB;
        vuA.x += wu1 * vA0; vuA.y += wu1 * vA1; vuA.z += wu1 * vA2;
        vkA.x += wa1 * vA0; vkA.y += wa1 * vA1; vkA.z += wa1 * vA2;
        vuB.x += wu1 * vB0; vuB.y += wu1 * vB1; vuB.z += wu1 * vB2;
        vkB.x += wb1 * vB0; vkB.y += wb1 * vB1; vkB.z += wb1 * vB2;
    }
    int nA = n0 + la, nB = n0 + lb;
    d_up[nA * 64 + g]   = make_float4(uA * INV, vuA.x * INV, vuA.y * INV, vuA.z * INV);
    d_skip[nA * 64 + g] = make_float4(skA * INV, vkA.x * INV, vkA.y * INV, vkA.z * INV);
    d_up[nB * 64 + g]   = make_float4(uB * INV, vuB.x * INV, vuB.y * INV, vuB.z * INV);
    d_skip[nB * 64 + g] = make_float4(skB * INV, vkB.x * INV, vkB.y * INV, vkB.z * INV);
}

// ---- kB: persistent edge kernel (radial MLP + TP + scatter) ----
constexpr int SMB_FLOATS = 512 + 4096 + 4096 + 16384 + 4096 + 4096 + 512 + 192;
constexpr int SMB_BYTES  = SMB_FLOATS * 4 + 128 * 4;

__device__ __forceinline__ void layer64(const float* __restrict__ in,
                                        const float* __restrict__ W,
                                        float* __restrict__ out,
                                        int fq, int eh) {
    int ea = eh * 2, eb = ea + 1;
    float ax = 0, ay = 0, az = 0, aw = 0, bx = 0, by = 0, bz = 0, bw = 0;
    #pragma unroll 8
    for (int k = 0; k < 64; k++) {
        float4 w = *(const float4*)(W + k * 64 + fq * 4);
        float a0 = in[ea * 64 + k];
        float a1 = in[eb * 64 + k];
        ax += w.x * a0; ay += w.y * a0; az += w.z * a0; aw += w.w * a0;
        bx += w.x * a1; by += w.y * a1; bz += w.z * a1; bw += w.w * a1;
    }
    *(float4*)(out + ea * 64 + fq * 4) = make_float4(silu(ax), silu(ay), silu(az), silu(aw));
    *(float4*)(out + eb * 64 + fq * 4) = make_float4(silu(bx), silu(by), silu(bz), silu(bw));
}

__global__ void __launch_bounds__(512, 1) kB(
    const float* __restrict__ vectors, const float* __restrict__ radial,
    const int* __restrict__ senders, const int* __restrict__ receivers,
    const float* __restrict__ R1, const float* __restrict__ R2,
    const float* __restrict__ R3, const float* __restrict__ R4) {
    extern __shared__ __align__(16) float sm[];
    float* sR1 = sm;            // 512
    float* sR2 = sm + 512;      // 4096
    float* sR3 = sm + 4608;     // 4096
    float* sR4 = sm + 8704;     // 16384 (repacked [k][f][p])
    float* sA  = sm + 25088;    // 4096
    float* sB  = sm + 29184;    // 4096
    float* sRe = sm + 33280;    // 512
    float* sU  = sm + 33792;    // 192
    int*   sSend = (int*)(sm + SMB_FLOATS);
    int*   sRecv = sSend + 64;

    int tid = threadIdx.x;
    // stage weights once per CTA
    sR1[tid] = R1[tid];
    for (int i = tid; i < 4096; i += 512) sR2[i] = R2[i];
    for (int i = tid; i < 4096; i += 512) sR3[i] = R3[i];
    for (int i = tid; i < 16384; i += 512) {
        int k = i >> 8, j = i & 255;
        sR4[((k << 6) + (j & 63)) * 4 + (j >> 6)] = R4[i];
    }
    __syncthreads();

    int fq = tid & 15, eh = tid >> 4;   // mapping for L1..L3
    int f  = tid & 63, eq = tid >> 6;   // mapping for L4+TP

    for (int t = blockIdx.x; t < Ee / 64; t += gridDim.x) {
        int e0 = t * 64;
        sRe[tid] = radial[e0 * 8 + tid];
        if (tid < 64) {
            int e = e0 + tid;
            sSend[tid] = senders[e];
            sRecv[tid] = receivers[e];
            float vx = vectors[e * 3 + 0], vy = vectors[e * 3 + 1], vz = vectors[e * 3 + 2];
            float rin = rsqrtf(vx * vx + vy * vy + vz * vz);
            sU[tid * 3 + 0] = vx * rin; sU[tid * 3 + 1] = vy * rin; sU[tid * 3 + 2] = vz * rin;
        }
        __syncthreads();

        // L1: (64e,8) @ (8,64) -> silu -> sA
        {
            int ea = eh * 2, eb = ea + 1;
            float ax = 0, ay = 0, az = 0, aw = 0, bx = 0, by = 0, bz = 0, bw = 0;
            #pragma unroll
            for (int d = 0; d < 8; d++) {
                float4 w = *(const float4*)(sR1 + d * 64 + fq * 4);
                float a0 = sRe[ea * 8 + d];
                float a1 = sRe[eb * 8 + d];
                ax += w.x * a0; ay += w.y * a0; az += w.z * a0; aw += w.w * a0;
                bx += w.x * a1; by += w.y * a1; bz += w.z * a1; bw += w.w * a1;
            }
            *(float4*)(sA + ea * 64 + fq * 4) = make_float4(silu(ax), silu(ay), silu(az), silu(aw));
            *(float4*)(sA + eb * 64 + fq * 4) = make_float4(silu(bx), silu(by), silu(bz), silu(bw));
        }
        __syncthreads();
        layer64(sA, sR2, sB, fq, eh);   // L2
        __syncthreads();
        layer64(sB, sR3, sA, fq, eh);   // L3
        __syncthreads();

        // L4 (4 paths) fused with tensor product + atomic scatter
        {
            float4 acc[8];
            #pragma unroll
            for (int j = 0; j < 8; j++) acc[j] = make_float4(0.f, 0.f, 0.f, 0.f);
            #pragma unroll 8
            for (int k = 0; k < 64; k++) {
                float4 w = *(const float4*)(sR4 + (k * 64 + f) * 4);
                #pragma unroll
                for (int j = 0; j < 8; j++) {
                    float a = sA[(eq * 8 + j) * 64 + k];
                    acc[j].x += w.x * a; acc[j].y += w.y * a;
                    acc[j].z += w.z * a; acc[j].w += w.w * a;
                }
            }
            #pragma unroll
            for (int j = 0; j < 8; j++) {
                int el = eq * 8 + j;
                int s = sSend[el], r = sRecv[el];
                float4 up = __ldg(&d_up[s * 64 + f]);
                float ux = sU[el * 3 + 0], uy = sU[el * 3 + 1], uz = sU[el * 3 + 2];
                float dot = up.y * ux + up.z * uy + up.w * uz;
                float ms  = acc[j].x * up.x + acc[j].y * dot;
                float c   = acc[j].w * up.x;
                float mv0 = acc[j].z * up.y + c * ux;
                float mv1 = acc[j].z * up.z + c * uy;
                float mv2 = acc[j].z * up.w + c * uz;
                float* dst = ((float*)d_acc) + (r * 64 + f) * 4;
                atomicAdd(dst + 0, ms);
                atomicAdd(dst + 1, mv0);
                atomicAdd(dst + 2, mv1);
                atomicAdd(dst + 3, mv2);
            }
        }
        __syncthreads();
    }
}

// ---- kC: linear_down + symmetric contraction + linear_sc + skip + readout ----
__global__ void __launch_bounds__(256) kC(
    const float* __restrict__ Wd0, const float* __restrict__ Wd1,
    const float* __restrict__ Wl0, const float* __restrict__ Wl1,
    const float* __restrict__ Wr, float* __restrict__ out) {
    __shared__ __align__(16) float bufA[2048];
    __shared__ __align__(16) float bufB[2048];
    __shared__ int zc[8];
    __shared__ float red[8];
    int tid = threadIdx.x;
    int n0 = blockIdx.x * 8;

    const float* accf = (const float*)d_acc;
    for (int i = tid; i < 2048; i += 256) bufA[i] = accf[n0 * 256 + i] * EPSC;
    if (tid < 8) {
        int n = n0 + tid, z = 0;
        #pragma unroll
        for (int q = 1; q < Zs; q++) z += (n >= d_cum[q]);
        zc[tid] = z;
        red[tid] = 0.f;
    }
    __syncthreads();

    int g = tid & 63, grp = tid >> 6;
    int la = grp * 2, lb = la + 1;

    // stage1: linear_down (packed)
    {
        float sa = 0, sb = 0; float3 va = {0,0,0}, vb = {0,0,0};
        #pragma unroll 4
        for (int fi = 0; fi < 64; fi++) {
            float w0 = Wd0[fi * 64 + g], w1 = Wd1[fi * 64 + g];
            float4 aA = *(const float4*)(bufA + (la * 64 + fi) * 4);
            float4 aB = *(const float4*)(bufA + (lb * 64 + fi) * 4);
            sa += w0 * aA.x; va.x += w1 * aA.y; va.y += w1 * aA.z; va.z += w1 * aA.w;
            sb += w0 * aB.x; vb.x += w1 * aB.y; vb.y += w1 * aB.z; vb.z += w1 * aB.w;
        }
        *(float4*)(bufB + (la * 64 + g) * 4) = make_float4(sa * INV, va.x * INV, va.y * INV, va.z * INV);
        *(float4*)(bufB + (lb * 64 + g) * 4) = make_float4(sb * INV, vb.x * INV, vb.y * INV, vb.z * INV);
    }
    __syncthreads();

    // stage2: symmetric contraction (elementwise)
    for (int it = tid; it < 512; it += 256) {
        int nl = it >> 6, fi = it & 63;
        float4 h = *(const float4*)(bufB + it * 4);
        const float* w = d_wsc + zc[nl] * 576 + fi;
        float hs = h.x;
        float vv = h.y * h.y + h.z * h.z + h.w * h.w;
        float hs2 = hs * hs;
        float cs = w[0] * hs + w[64] * hs2 + w[128] * vv + w[192] * (hs2 * hs) + w[256] * (hs * vv);
        float cf = w[320] + w[384] * hs + w[448] * hs2 + w[512] * vv;
        *(float4*)(bufA + it * 4) = make_float4(cs, h.y * cf, h.z * cf, h.w * cf);
    }
    __syncthreads();

    // stage3: linear_sc + skip + outputs + readout partial
    {
        float sa = 0, sb = 0; float3 va = {0,0,0}, vb = {0,0,0};
        #pragma unroll 4
        for (int fi = 0; fi < 64; fi++) {
            float w0 = Wl0[fi * 64 + g], w1 = Wl1[fi * 64 + g];
            float4 aA = *(const float4*)(bufA + (la * 64 + fi) * 4);
            float4 aB = *(const float4*)(bufA + (lb * 64 + fi) * 4);
            sa += w0 * aA.x; va.x += w1 * aA.y; va.y += w1 * aA.z; va.z += w1 * aA.w;
            sb += w0 * aB.x; vb.x += w1 * aB.y; vb.y += w1 * aB.z; vb.z += w1 * aB.w;
        }
        int nA = n0 + la, nB = n0 + lb;
        float4 skA = d_skip[nA * 64 + g];
        float4 skB = d_skip[nB * 64 + g];
        float hsA = sa * INV + skA.x;
        float hv0A = va.x * INV + skA.y, hv1A = va.y * INV + skA.z, hv2A = va.z * INV + skA.w;
        float hsB = sb * INV + skB.x;
        float hv0B = vb.x * INV + skB.y, hv1B = vb.y * INV + skB.z, hv2B = vb.z * INV + skB.w;

        out[Nn + nA * 64 + g] = hsA;
        out[Nn + nB * 64 + g] = hsB;
        float* ohv = out + Nn + Nn * 64;
        ohv[(nA * 64 + g) * 3 + 0] = hv0A;
        ohv[(nA * 64 + g) * 3 + 1] = hv1A;
        ohv[(nA * 64 + g) * 3 + 2] = hv2A;
        ohv[(nB * 64 + g) * 3 + 0] = hv0B;
        ohv[(nB * 64 + g) * 3 + 1] = hv1B;
        ohv[(nB * 64 + g) * 3 + 2] = hv2B;

        float wr = Wr[g];
        atomicAdd(&red[la], hsA * wr);
        atomicAdd(&red[lb], hsB * wr);
    }
    __syncthreads();
    if (tid < 8) out[n0 + tid] = red[tid] * INV;
}

extern "C" void kernel_launch(void* const* d_in, const int* in_sizes, int n_in,
                              void* d_out, int out_size) {
    (void)in_sizes; (void)n_in; (void)out_size;
    const float* vectors   = (const float*)d_in[0];
    const float* node_s    = (const float*)d_in[1];
    const float* node_v    = (const float*)d_in[2];
    const float* radial    = (const float*)d_in[3];
    const int*   senders   = (const int*)d_in[4];
    const int*   receivers = (const int*)d_in[5];
    const int*   counts    = (const int*)d_in[6];
    const float* Wup0 = (const float*)d_in[7];
    const float* Wup1 = (const float*)d_in[8];
    const float* R1   = (const float*)d_in[9];
    const float* R2   = (const float*)d_in[10];
    const float* R3   = (const float*)d_in[11];
    const float* R4   = (const float*)d_in[12];
    const float* Wd0  = (const float*)d_in[13];
    const float* Wd1  = (const float*)d_in[14];
    const float* Ws0  = (const float*)d_in[15];
    const float* Ws1  = (const float*)d_in[16];
    const float* Wsc  = (const float*)d_in[17];
    const float* Proj = (const float*)d_in[18];
    const float* Wl0  = (const float*)d_in[19];
    const float* Wl1  = (const float*)d_in[20];
    const float* Wr   = (const float*)d_in[21];
    float* out = (float*)d_out;

    cudaFuncSetAttribute(kB, cudaFuncAttributeMaxDynamicSharedMemorySize, SMB_BYTES);

    k0<<<1, 256>>>(counts, Wsc, Proj);
    kA<<<Nn / 8, 256>>>(node_s, node_v, Wup0, Wup1, Ws0, Ws1);
    kB<<<152, 512, SMB_BYTES>>>(vectors, radial, senders, receivers, R1, R2, R3, R4);
    kC<<<Nn / 8, 256>>>(Wd0, Wd1, Wl0, Wl1, Wr, out);
}

// round 2
// speedup vs baseline: 1.0358x; 1.0358x over previous
#include <cuda_runtime.h>

#define Nn 20000
#define Fc 64
#define Zs 10
#define Ee 320000

// ---- scratch (device globals; no allocation) ----
__device__ float4 d_up[Nn * Fc];      // packed (s, v0, v1, v2), inv folded
__device__ float4 d_skip[Nn * Fc];    // packed skip, inv folded
__device__ float4 d_acc[Nn * Fc];     // message accumulator
__device__ float  d_wsc[Zs * 9 * Fc]; // Wsc projected: [(z*9+b)*64+u]
__device__ int    d_cum[Zs + 1];

constexpr float INV  = 0.125f;  // 1/sqrt(64)
constexpr float EPSC = 0.25f;

typedef unsigned long long ull;

__device__ __forceinline__ float silu(float x) {
    return __fdividef(x, 1.0f + __expf(-x));
}
__device__ __forceinline__ ull pk2(float a, float b) {
    ull r; asm("mov.b64 %0, {%1, %2};" : "=l"(r) : "f"(a), "f"(b)); return r;
}
__device__ __forceinline__ void upk2(ull v, float& a, float& b) {
    asm("mov.b64 {%0, %1}, %2;" : "=f"(a), "=f"(b) : "l"(v));
}
__device__ __forceinline__ void fma2p(ull& d, ull a, ull b) {
    asm("fma.rn.f32x2 %0, %1, %2, %0;" : "+l"(d) : "l"(a), "l"(b));
}
__device__ __forceinline__ void red4(float* p, float a, float b, float c, float d) {
    ull gp = (ull)__cvta_generic_to_global(p);
    asm volatile("red.global.add.v4.f32 [%0], {%1, %2, %3, %4};"
                 :: "l"(gp), "f"(a), "f"(b), "f"(c), "f"(d) : "memory");
}

// ---- k0: species prefix + Wsc @ Proj ----
__global__ void k0(const int* __restrict__ counts,
                   const float* __restrict__ Wsc,
                   const float* __restrict__ Proj) {
    int tid = threadIdx.x;
    if (tid == 0) {
        int c = 0; d_cum[0] = 0;
        for (int z = 0; z < Zs; z++) { c += counts[z]; d_cum[z + 1] = c; }
    }
    for (int it = tid; it < Zs * 9 * Fc; it += blockDim.x) {
        int z = it / (9 * Fc);
        int rem = it % (9 * Fc);
        int b = rem / Fc, u = rem % Fc;
        float s = 0.f;
        #pragma unroll
        for (int p = 0; p < 9; p++)
            s += Wsc[(z * 9 + p) * Fc + u] * Proj[p * 9 + b];
        d_wsc[it] = s;
    }
}

// ---- kA: linear_up + species skip, 64-node tiles, f32x2 ----
constexpr int SMA_BYTES = 32768 * 4;
__global__ void __launch_bounds__(512) kA(
    const float* __restrict__ node_s, const float* __restrict__ node_v,
    const float* __restrict__ Wup0, const float* __restrict__ Wup1,
    const float* __restrict__ Ws0, const float* __restrict__ Ws1) {
    extern __shared__ __align__(16) float sm[];
    float* sWup0 = sm;            // 4096
    float* sWup1 = sm + 4096;
    float* sA0   = sm + 8192;
    float* sA1   = sm + 12288;
    float* sB0   = sm + 16384;
    float* sB1   = sm + 20480;
    float* sS    = sm + 24576;    // 2048
    float* sV    = sm + 26624;    // 6144

    int tid = threadIdx.x;
    int n0 = blockIdx.x * 64;

    // zero accumulator rows for this tile
    {
        float* accf = (float*)d_acc;
        int lim = min(Nn, n0 + 64) * 256;
        for (int i = n0 * 256 + tid; i < lim; i += 512) accf[i] = 0.f;
    }
    int zA = 0, zB = 0;
    {
        int nLast = min(n0 + 63, Nn - 1);
        #pragma unroll
        for (int q = 1; q < Zs; q++) { zA += (n0 >= d_cum[q]); zB += (nLast >= d_cum[q]); }
    }
    int boundary = d_cum[zA + 1];
    for (int i = tid; i < 4096; i += 512) {
        sWup0[i] = Wup0[i]; sWup1[i] = Wup1[i];
        sA0[i] = Ws0[zA * 4096 + i]; sA1[i] = Ws1[zA * 4096 + i];
        sB0[i] = Ws0[zB * 4096 + i]; sB1[i] = Ws1[zB * 4096 + i];
    }
    __syncthreads();

    for (int w = 0; w < 2; w++) {
        int nb = n0 + w * 32;
        for (int i = tid; i < 2048; i += 512) {
            int n = nb + (i >> 6);
            sS[i] = (n < Nn) ? node_s[n * 64 + (i & 63)] : 0.f;
        }
        for (int i = tid; i < 6144; i += 512) {
            int n = nb + i / 192;
            sV[i] = (n < Nn) ? node_v[n * 192 + i % 192] : 0.f;
        }
        __syncthreads();

        int nl = tid >> 4;
        int n  = nb + nl;
        int g0 = (tid & 15) * 4;
        const float* ws0 = (n < boundary) ? sA0 : sB0;
        const float* ws1 = (n < boundary) ? sA1 : sB1;
        const float* sSp = sS + nl * 64;
        const float* sVp = sV + nl * 192;

        ull us[2] = {0,0}, ks[2] = {0,0};
        ull uv[3][2] = {{0,0},{0,0},{0,0}};
        ull kv[3][2] = {{0,0},{0,0},{0,0}};
        #pragma unroll 8
        for (int f = 0; f < 64; f++) {
            ulonglong2 w0 = *(const ulonglong2*)(sWup0 + f * 64 + g0);
            ulonglong2 w1 = *(const ulonglong2*)(sWup1 + f * 64 + g0);
            ulonglong2 q0 = *(const ulonglong2*)(ws0 + f * 64 + g0);
            ulonglong2 q1 = *(const ulonglong2*)(ws1 + f * 64 + g0);
            float s = sSp[f];
            float v0 = sVp[f*3], v1 = sVp[f*3+1], v2 = sVp[f*3+2];
            ull ps = pk2(s, s);
            ull p0 = pk2(v0, v0), p1 = pk2(v1, v1), p2 = pk2(v2, v2);
            fma2p(us[0], w0.x, ps); fma2p(us[1], w0.y, ps);
            fma2p(uv[0][0], w1.x, p0); fma2p(uv[0][1], w1.y, p0);
            fma2p(uv[1][0], w1.x, p1); fma2p(uv[1][1], w1.y, p1);
            fma2p(uv[2][0], w1.x, p2); fma2p(uv[2][1], w1.y, p2);
            fma2p(ks[0], q0.x, ps); fma2p(ks[1], q0.y, ps);
            fma2p(kv[0][0], q1.x, p0); fma2p(kv[0][1], q1.y, p0);
            fma2p(kv[1][0], q1.x, p1); fma2p(kv[1][1], q1.y, p1);
            fma2p(kv[2][0], q1.x, p2); fma2p(kv[2][1], q1.y, p2);
        }
        if (n < Nn) {
            float a[4], x[4], y[4], z[4];
            float b[4], u[4], v[4], t[4];
            upk2(us[0], a[0], a[1]); upk2(us[1], a[2], a[3]);
            upk2(uv[0][0], x[0], x[1]); upk2(uv[0][1], x[2], x[3]);
            upk2(uv[1][0], y[0], y[1]); upk2(uv[1][1], y[2], y[3]);
            upk2(uv[2][0], z[0], z[1]); upk2(uv[2][1], z[2], z[3]);
            upk2(ks[0], b[0], b[1]); upk2(ks[1], b[2], b[3]);
            upk2(kv[0][0], u[0], u[1]); upk2(kv[0][1], u[2], u[3]);
            upk2(kv[1][0], v[0], v[1]); upk2(kv[1][1], v[2], v[3]);
            upk2(kv[2][0], t[0], t[1]); upk2(kv[2][1], t[2], t[3]);
            #pragma unroll
            for (int j = 0; j < 4; j++) {
                d_up[n * 64 + g0 + j]   = make_float4(a[j]*INV, x[j]*INV, y[j]*INV, z[j]*INV);
                d_skip[n * 64 + g0 + j] = make_float4(b[j]*INV, u[j]*INV, v[j]*INV, t[j]*INV);
            }
        }
        __syncthreads();
    }
}

// ---- kB: persistent edge kernel (radial MLP + TP + scatter), f32x2 ----
constexpr int SMB_FLOATS = 512 + 4096 + 4096 + 16384 + 8192 + 8192 + 1024 + 384;
constexpr int SMB_BYTES  = SMB_FLOATS * 4 + 256 * 4;

__device__ __forceinline__ void store8(float* d, ull* a) {
    float x0,x1,x2,x3,x4,x5,x6,x7;
    upk2(a[0], x0, x1); upk2(a[1], x2, x3);
    upk2(a[2], x4, x5); upk2(a[3], x6, x7);
    *(float4*)d       = make_float4(silu(x0), silu(x1), silu(x2), silu(x3));
    *(float4*)(d + 4) = make_float4(silu(x4), silu(x5), silu(x6), silu(x7));
}

template<int SIN, int K>
__device__ __forceinline__ void layer2(const float* __restrict__ in,
                                       const float* __restrict__ W,
                                       float* __restrict__ out,
                                       int og8, int eg) {
    const float* in0 = in + (2 * eg) * SIN;
    const float* in1 = in0 + SIN;
    ull a0[4] = {0,0,0,0}, a1[4] = {0,0,0,0};
    #pragma unroll 8
    for (int k = 0; k < K; k++) {
        ulonglong2 wA = *(const ulonglong2*)(W + k * 64 + og8);
        ulonglong2 wB = *(const ulonglong2*)(W + k * 64 + og8 + 4);
        ull p0 = pk2(in0[k], in0[k]);
        ull p1 = pk2(in1[k], in1[k]);
        fma2p(a0[0], wA.x, p0); fma2p(a0[1], wA.y, p0);
        fma2p(a0[2], wB.x, p0); fma2p(a0[3], wB.y, p0);
        fma2p(a1[0], wA.x, p1); fma2p(a1[1], wA.y, p1);
        fma2p(a1[2], wB.x, p1); fma2p(a1[3], wB.y, p1);
    }
    store8(out + (2 * eg) * 64 + og8, a0);
    store8(out + (2 * eg + 1) * 64 + og8, a1);
}

__global__ void __launch_bounds__(512, 1) kB(
    const float* __restrict__ vectors, const float* __restrict__ radial,
    const int* __restrict__ senders, const int* __restrict__ receivers,
    const float* __restrict__ R1, const float* __restrict__ R2,
    const float* __restrict__ R3, const float* __restrict__ R4) {
    extern __shared__ __align__(16) float sm[];
    float* sR1 = sm;             // 512
    float* sR2 = sm + 512;       // 4096
    float* sR3 = sm + 4608;      // 4096
    float* sR4 = sm + 8704;      // 16384 repacked [k][f][p]
    float* sA  = sm + 25088;     // 8192 (128 x 64)
    float* sB  = sm + 33280;     // 8192
    float* sRe = sm + 41472;     // 1024 (128 x 8)
    float* sU  = sm + 42496;     // 384
    int* sSend = (int*)(sm + SMB_FLOATS);
    int* sRecv = sSend + 128;

    int tid = threadIdx.x;
    sR1[tid] = R1[tid];
    for (int i = tid; i < 4096; i += 512) { sR2[i] = R2[i]; sR3[i] = R3[i]; }
    for (int i = tid; i < 16384; i += 512) {
        int k = i >> 8, j = i & 255;
        sR4[((k << 6) + (j & 63)) * 4 + (j >> 6)] = R4[i];
    }
    __syncthreads();

    int og8 = (tid & 7) * 8;
    int eg  = tid >> 3;
    int f   = tid & 63;
    int eq  = tid >> 6;

    for (int t = blockIdx.x; t < Ee / 128; t += gridDim.x) {
        int e0 = t * 128;
        for (int i = tid; i < 1024; i += 512) sRe[i] = radial[e0 * 8 + i];
        if (tid < 128) {
            int e = e0 + tid;
            sSend[tid] = senders[e];
            sRecv[tid] = receivers[e];
            float vx = vectors[e*3], vy = vectors[e*3+1], vz = vectors[e*3+2];
            float rin = rsqrtf(vx*vx + vy*vy + vz*vz);
            sU[tid*3] = vx*rin; sU[tid*3+1] = vy*rin; sU[tid*3+2] = vz*rin;
        }
        __syncthreads();
        layer2<8, 8>(sRe, sR1, sA, og8, eg);
        __syncthreads();
        layer2<64, 64>(sA, sR2, sB, og8, eg);
        __syncthreads();
        layer2<64, 64>(sB, sR3, sA, og8, eg);
        __syncthreads();

        // L4 (4 paths) fused with tensor product + vectorized red scatter
        #pragma unroll 1
        for (int pass = 0; pass < 2; pass++) {
            int eb = eq * 16 + pass * 8;
            ull acc[8][2];
            #pragma unroll
            for (int j = 0; j < 8; j++) { acc[j][0] = 0; acc[j][1] = 0; }
            #pragma unroll 8
            for (int k = 0; k < 64; k++) {
                ulonglong2 w = *(const ulonglong2*)(sR4 + (k * 64 + f) * 4);
                #pragma unroll
                for (int j = 0; j < 8; j++) {
                    float a = sA[(eb + j) * 64 + k];
                    ull pa = pk2(a, a);
                    fma2p(acc[j][0], w.x, pa);
                    fma2p(acc[j][1], w.y, pa);
                }
            }
            #pragma unroll
            for (int j = 0; j < 8; j++) {
                int el = eb + j;
                float w0, w1, w2, w3;
                upk2(acc[j][0], w0, w1);
                upk2(acc[j][1], w2, w3);
                int s = sSend[el], r = sRecv[el];
                float4 up = __ldg(&d_up[s * 64 + f]);
                float ux = sU[el*3], uy = sU[el*3+1], uz = sU[el*3+2];
                float dot = up.y*ux + up.z*uy + up.w*uz;
                float ms = w0 * up.x + w1 * dot;
                float c  = w3 * up.x;
                red4((float*)(d_acc + (r * 64 + f)),
                     ms, w2*up.y + c*ux, w2*up.z + c*uy, w2*up.w + c*uz);
            }
        }
        __syncthreads();
    }
}

// ---- kC: linear_down + symmetric contraction + linear_sc + skip + readout ----
constexpr int SMC_BYTES = (16384 + 8192 + 8192 + 64) * 4;
__global__ void __launch_bounds__(512) kC(
    const float* __restrict__ Wd0, const float* __restrict__ Wd1,
    const float* __restrict__ Wl0, const float* __restrict__ Wl1,
    const float* __restrict__ Wr, float* __restrict__ out) {
    extern __shared__ __align__(16) float sm[];
    float* sWd0 = sm;
    float* sWd1 = sm + 4096;
    float* sWl0 = sm + 8192;
    float* sWl1 = sm + 12288;
    float4* sIn  = (float4*)(sm + 16384);  // 2048 float4
    float4* sMid = (float4*)(sm + 24576);  // 2048 float4
    float* sWr = sm + 32768;

    int tid = threadIdx.x;
    int n0 = blockIdx.x * 64;
    for (int i = tid; i < 4096; i += 512) {
        sWd0[i] = Wd0[i]; sWd1[i] = Wd1[i];
        sWl0[i] = Wl0[i]; sWl1[i] = Wl1[i];
    }
    if (tid < 64) sWr[tid] = Wr[tid];
    __syncthreads();

    float* ohv = out + Nn + Nn * 64;

    for (int w = 0; w < 2; w++) {
        int nb = n0 + w * 32;
        for (int i = tid; i < 2048; i += 512) {
            int n = nb + (i >> 6);
            float4 t = (n < Nn) ? d_acc[n * 64 + (i & 63)] : make_float4(0,0,0,0);
            sIn[i] = make_float4(t.x*EPSC, t.y*EPSC, t.z*EPSC, t.w*EPSC);
        }
        __syncthreads();

        int nl = tid >> 4;
        int n  = nb + nl;
        int g0 = (tid & 15) * 4;
        bool valid = (n < Nn);

        // stage1: linear_down
        ull hs_[2] = {0,0};
        ull hv_[3][2] = {{0,0},{0,0},{0,0}};
        #pragma unroll 8
        for (int fi = 0; fi < 64; fi++) {
            ulonglong2 w0 = *(const ulonglong2*)(sWd0 + fi * 64 + g0);
            ulonglong2 w1 = *(const ulonglong2*)(sWd1 + fi * 64 + g0);
            float4 a = sIn[nl * 64 + fi];
            ull ps = pk2(a.x, a.x);
            ull p0 = pk2(a.y, a.y), p1 = pk2(a.z, a.z), p2 = pk2(a.w, a.w);
            fma2p(hs_[0], w0.x, ps); fma2p(hs_[1], w0.y, ps);
            fma2p(hv_[0][0], w1.x, p0); fma2p(hv_[0][1], w1.y, p0);
            fma2p(hv_[1][0], w1.x, p1); fma2p(hv_[1][1], w1.y, p1);
            fma2p(hv_[2][0], w1.x, p2); fma2p(hv_[2][1], w1.y, p2);
        }
        float hs[4], hx[4], hy[4], hz[4];
        upk2(hs_[0], hs[0], hs[1]); upk2(hs_[1], hs[2], hs[3]);
        upk2(hv_[0][0], hx[0], hx[1]); upk2(hv_[0][1], hx[2], hx[3]);
        upk2(hv_[1][0], hy[0], hy[1]); upk2(hv_[1][1], hy[2], hy[3]);
        upk2(hv_[2][0], hz[0], hz[1]); upk2(hv_[2][1], hz[2], hz[3]);

        // stage2: symmetric contraction (elementwise)
        if (valid) {
            int z = 0;
            #pragma unroll
            for (int q = 1; q < Zs; q++) z += (n >= d_cum[q]);
            const float* wp = d_wsc + z * 576 + g0;
            #pragma unroll
            for (int j = 0; j < 4; j++) {
                float h = hs[j] * INV;
                float x = hx[j] * INV, y = hy[j] * INV, zc = hz[j] * INV;
                float vv = x*x + y*y + zc*zc;
                float h2 = h * h;
                const float* q2 = wp + j;
                float cs = q2[0]*h + q2[64]*h2 + q2[128]*vv + q2[192]*(h2*h) + q2[256]*(h*vv);
                float cf = q2[320] + q2[384]*h + q2[448]*h2 + q2[512]*vv;
                sMid[nl * 64 + g0 + j] = make_float4(cs, x*cf, y*cf, zc*cf);
            }
        }
        __syncthreads();

        // stage3: linear_sc + skip + outputs + readout
        float partial = 0.f;
        if (valid) {
            ull cs_[2] = {0,0};
            ull cv_[3][2] = {{0,0},{0,0},{0,0}};
            #pragma unroll 8
            for (int fi = 0; fi < 64; fi++) {
                ulonglong2 w0 = *(const ulonglong2*)(sWl0 + fi * 64 + g0);
                ulonglong2 w1 = *(const ulonglong2*)(sWl1 + fi * 64 + g0);
                float4 a = sMid[nl * 64 + fi];
                ull ps = pk2(a.x, a.x);
                ull p0 = pk2(a.y, a.y), p1 = pk2(a.z, a.z), p2 = pk2(a.w, a.w);
                fma2p(cs_[0], w0.x, ps); fma2p(cs_[1], w0.y, ps);
                fma2p(cv_[0][0], w1.x, p0); fma2p(cv_[0][1], w1.y, p0);
                fma2p(cv_[1][0], w1.x, p1); fma2p(cv_[1][1], w1.y, p1);
                fma2p(cv_[2][0], w1.x, p2); fma2p(cv_[2][1], w1.y, p2);
            }
            float cs[4], cx[4], cy[4], cz[4];
            upk2(cs_[0], cs[0], cs[1]); upk2(cs_[1], cs[2], cs[3]);
            upk2(cv_[0][0], cx[0], cx[1]); upk2(cv_[0][1], cx[2], cx[3]);
            upk2(cv_[1][0], cy[0], cy[1]); upk2(cv_[1][1], cy[2], cy[3]);
            upk2(cv_[2][0], cz[0], cz[1]); upk2(cv_[2][1], cz[2], cz[3]);
            #pragma unroll
            for (int j = 0; j < 4; j++) {
                int g = g0 + j;
                float4 sk = d_skip[n * 64 + g];
                float hso = cs[j]*INV + sk.x;
                float v0 = cx[j]*INV + sk.y;
                float v1 = cy[j]*INV + sk.z;
                float v2 = cz[j]*INV + sk.w;
                out[Nn + n * 64 + g] = hso;
                ohv[(n * 64 + g) * 3 + 0] = v0;
                ohv[(n * 64 + g) * 3 + 1] = v1;
                ohv[(n * 64 + g) * 3 + 2] = v2;
                partial += hso * sWr[g];
            }
        }
        partial += __shfl_down_sync(0xffffffffu, partial, 8, 16);
        partial += __shfl_down_sync(0xffffffffu, partial, 4, 16);
        partial += __shfl_down_sync(0xffffffffu, partial, 2, 16);
        partial += __shfl_down_sync(0xffffffffu, partial, 1, 16);
        if ((tid & 15) == 0 && valid) out[n] = partial * INV;
        __syncthreads();
    }
}

extern "C" void kernel_launch(void* const* d_in, const int* in_sizes, int n_in,
                              void* d_out, int out_size) {
    (void)in_sizes; (void)n_in; (void)out_size;
    const float* vectors   = (const float*)d_in[0];
    const float* node_s    = (const float*)d_in[1];
    const float* node_v    = (const float*)d_in[2];
    const float* radial    = (const float*)d_in[3];
    const int*   senders   = (const int*)d_in[4];
    const int*   receivers = (const int*)d_in[5];
    const int*   counts    = (const int*)d_in[6];
    const float* Wup0 = (const float*)d_in[7];
    const float* Wup1 = (const float*)d_in[8];
    const float* R1   = (const float*)d_in[9];
    const float* R2   = (const float*)d_in[10];
    const float* R3   = (const float*)d_in[11];
    const float* R4   = (const float*)d_in[12];
    const float* Wd0  = (const float*)d_in[13];
    const float* Wd1  = (const float*)d_in[14];
    const float* Ws0  = (const float*)d_in[15];
    const float* Ws1  = (const float*)d_in[16];
    const float* Wsc  = (const float*)d_in[17];
    const float* Proj = (const float*)d_in[18];
    const float* Wl0  = (const float*)d_in[19];
    const float* Wl1  = (const float*)d_in[20];
    const float* Wr   = (const float*)d_in[21];
    float* out = (float*)d_out;

    cudaFuncSetAttribute(kA, cudaFuncAttributeMaxDynamicSharedMemorySize, SMA_BYTES);
    cudaFuncSetAttribute(kB, cudaFuncAttributeMaxDynamicSharedMemorySize, SMB_BYTES);
    cudaFuncSetAttribute(kC, cudaFuncAttributeMaxDynamicSharedMemorySize, SMC_BYTES);

    k0<<<1, 256>>>(counts, Wsc, Proj);
    kA<<<(Nn + 63) / 64, 512, SMA_BYTES>>>(node_s, node_v, Wup0, Wup1, Ws0, Ws1);
    kB<<<152, 512, SMB_BYTES>>>(vectors, radial, senders, receivers, R1, R2, R3, R4);
    kC<<<(Nn + 63) / 64, 512, SMC_BYTES>>>(Wd0, Wd1, Wl0, Wl1, Wr, out);
}